// round 10
// baseline (speedup 1.0000x reference)
#include <cuda_runtime.h>
#include <cuda_bf16.h>
#include <cstdint>

// ---------------------------------------------------------------------------
// Problem constants
// ---------------------------------------------------------------------------
#define BB   128          // batch
#define TT   512          // time steps
#define HH   512          // hidden
#define EE   512          // embed dim
#define VOUT 30000

// output layout (flattened tuple): logits, h1, cw, aw, ccov, acov
#define OFF_H1   (BB * VOUT)
#define OFF_CW   (OFF_H1 + BB * HH)
#define OFF_AW   (OFF_CW + BB * TT)
#define OFF_CCOV (OFF_AW + BB * TT)
#define OFF_ACOV (OFF_CCOV + BB * TT)

typedef unsigned long long ull;

// ---------------------------------------------------------------------------
// Scratch (static device globals — no allocation)
// ---------------------------------------------------------------------------
__device__ float g_spart[2][2][BB * TT];     // partial scores, 2 j-slabs of 256
__device__ float g_Hh[2][BB * HH];           // h0 @ W1^T + b_attn (summed)
__device__ float g_HhP[2][2][BB * HH];       // split-K partials
__device__ float g_u[2][HH];                 // W3 @ Wc
__device__ float g_x[BB * (EE + HH)];        // GRU input [emb, ctx]
__device__ float g_y[BB * (2 * HH)];         // [h1, ctx]
__device__ float g_gi[2][BB * 3 * HH];       // split-K partials
__device__ float g_gh[2][BB * 3 * HH];
// pre-converted, pre-swizzled bf16 tile images
__device__ __align__(16) unsigned char g_w2bf[2 * 2 * 8 * 65536];  // 2MB
__device__ __align__(16) unsigned char g_ybf[16 * 32768];          // 512KB

// ---------------------------------------------------------------------------
// FFMA2 helpers (small GEMMs)
// ---------------------------------------------------------------------------
__device__ __forceinline__ ull dup2f(float x) {
    ull r;
    asm("mov.b64 %0, {%1, %1};" : "=l"(r) : "f"(x));
    return r;
}
__device__ __forceinline__ ull ffma2(ull a, ull b, ull c) {
    ull d;
    asm("fma.rn.f32x2 %0, %1, %2, %3;" : "=l"(d) : "l"(a), "l"(b), "l"(c));
    return d;
}
__device__ __forceinline__ float2 unpack2(ull v) {
    float x, y;
    asm("mov.b64 {%0, %1}, %2;" : "=f"(x), "=f"(y) : "l"(v));
    return make_float2(x, y);
}

// ---------------------------------------------------------------------------
// Tensor-core + async-copy primitives (sm_80-era: no 'a' target gating)
// ---------------------------------------------------------------------------
__device__ __forceinline__ uint32_t smem_to_u32(const void* p) {
    uint32_t a;
    asm("{ .reg .u64 t; cvta.to.shared.u64 t, %1; cvt.u32.u64 %0, t; }"
        : "=r"(a) : "l"(p));
    return a;
}
__device__ __forceinline__ void ldsm4(uint32_t (&r)[4], uint32_t addr) {
    asm volatile("ldmatrix.sync.aligned.m8n8.x4.shared.b16 {%0,%1,%2,%3}, [%4];"
                 : "=r"(r[0]), "=r"(r[1]), "=r"(r[2]), "=r"(r[3]) : "r"(addr));
}
__device__ __forceinline__ void mma16816(float (&c)[4],
    const uint32_t (&a)[4], uint32_t b0, uint32_t b1)
{
    asm volatile(
        "mma.sync.aligned.m16n8k16.row.col.f32.bf16.bf16.f32 "
        "{%0,%1,%2,%3}, {%4,%5,%6,%7}, {%8,%9}, {%0,%1,%2,%3};"
        : "+f"(c[0]), "+f"(c[1]), "+f"(c[2]), "+f"(c[3])
        : "r"(a[0]), "r"(a[1]), "r"(a[2]), "r"(a[3]), "r"(b0), "r"(b1));
}
#define STS128(r0, r1, r2, r3, smem_addr) \
    asm volatile("st.shared.v4.b32 [%0], {%1, %2, %3, %4};" \
        :: "r"(smem_addr), "r"(r0), "r"(r1), "r"(r2), "r"(r3) : "memory")
#define CP_ASYNC16(dst, src) \
    asm volatile("cp.async.cg.shared.global [%0], [%1], 16;" \
        :: "r"(dst), "l"(src) : "memory")
#define CP_COMMIT() asm volatile("cp.async.commit_group;" ::: "memory")
#define CP_WAIT0()  asm volatile("cp.async.wait_group 0;" ::: "memory")

// stage layout (bytes): A_HI 0 (16K), A_LO 16K, B_HI 32K (32K), B_LO 64K
#define STAGE_BYTES 98304
#define MMA_SMEM (2 * STAGE_BYTES + 128)   // + alignment slack

// swizzled byte offset for (row, 16B-seg) in a [rows x 128B] tile
__device__ __forceinline__ uint32_t swadr(int row, int seg) {
    uint32_t off = (uint32_t)(row * 128 + seg * 16);
    return off ^ (((uint32_t)(row & 7)) << 4);
}

// fp32x8 -> bf16 hi/lo split of one 16B-seg (8 values)
__device__ __forceinline__ void split8(const float* __restrict__ s,
                                       uint32_t (&hp)[4], uint32_t (&lp)[4])
{
    float4 x0 = *reinterpret_cast<const float4*>(s);
    float4 x1 = *reinterpret_cast<const float4*>(s + 4);
    float xs[8] = {x0.x, x0.y, x0.z, x0.w, x1.x, x1.y, x1.z, x1.w};
    #pragma unroll
    for (int p = 0; p < 4; ++p) {
        float a0 = xs[2 * p], a1 = xs[2 * p + 1];
        __nv_bfloat162 h = __floats2bfloat162_rn(a0, a1);
        float r0f = a0 - __bfloat162float(h.x);
        float r1f = a1 - __bfloat162float(h.y);
        __nv_bfloat162 l = __floats2bfloat162_rn(r0f, r1f);
        hp[p] = *reinterpret_cast<uint32_t*>(&h);
        lp[p] = *reinterpret_cast<uint32_t*>(&l);
    }
}

// ---------------------------------------------------------------------------
// Split-bf16 (3-pass) 128x256 tile GEMM core on mma.sync.
//   C[128,256](fp32) = A[128,K] @ B[n0:n0+256, K]^T
//   APRE: A via cp.async from pre-swizzled bf16 image (chunk stride 32KB)
//   BPRE: B via cp.async from pre-swizzled bf16 image (chunk stride 64KB)
//   512 threads, 16 warps (4 wm x 4 wn), warp tile 32x64, double-buffered.
// ---------------------------------------------------------------------------
template <bool APRE, bool BPRE>
__device__ __forceinline__ void mma_core256(
    const float* __restrict__ Afp, int lda,
    const unsigned char* __restrict__ apre,
    const float* __restrict__ Bfp, int ldb, int n0, int brow_last,
    const unsigned char* __restrict__ bpre,
    int nchunks, uint32_t tb, float (&acc)[2][8][4])
{
    const int tid  = threadIdx.x;
    const int lane = tid & 31;
    const int wid  = tid >> 5;
    const int wm   = wid & 3;
    const int wn   = wid >> 2;
    const int g  = lane >> 3;
    const int lr = lane & 7;
    const int a_row = wm * 32 + lr + (g & 1) * 8;
    const int a_k8  = g >> 1;
    const int b_row = wn * 64 + (g >> 1) * 8 + lr;
    const int b_k8  = g & 1;

    auto load_chunk = [&](int c, uint32_t dst) {
        if (APRE) {
            const unsigned char* src = apre + (size_t)c * 32768;
            #pragma unroll
            for (int p = 0; p < 4; ++p) {
                int i = tid + p * 512;                 // 2048 x 16B = 32KB
                CP_ASYNC16(dst + i * 16, src + i * 16);
            }
        } else {
            #pragma unroll
            for (int p = 0; p < 2; ++p) {
                int u = tid + p * 512;                 // 1024 units
                int row = u >> 3, seg = u & 7;
                uint32_t hp[4], lp[4];
                split8(Afp + (size_t)row * lda + c * 64 + seg * 8, hp, lp);
                uint32_t sw = swadr(row, seg);
                STS128(hp[0], hp[1], hp[2], hp[3], dst + sw);
                STS128(lp[0], lp[1], lp[2], lp[3], dst + 16384 + sw);
            }
        }
        if (BPRE) {
            const unsigned char* src = bpre + (size_t)c * 65536;
            #pragma unroll
            for (int p = 0; p < 8; ++p) {
                int i = tid + p * 512;                 // 4096 x 16B = 64KB
                CP_ASYNC16(dst + 32768 + i * 16, src + i * 16);
            }
        } else {
            #pragma unroll
            for (int p = 0; p < 4; ++p) {
                int u = tid + p * 512;                 // 2048 units, 256 rows
                int row = u >> 3, seg = u & 7;
                int rg = n0 + row;
                if (rg > brow_last) rg = brow_last;
                uint32_t hp[4], lp[4];
                split8(Bfp + (size_t)rg * ldb + c * 64 + seg * 8, hp, lp);
                uint32_t sw = swadr(row, seg);
                STS128(hp[0], hp[1], hp[2], hp[3], dst + 32768 + sw);
                STS128(lp[0], lp[1], lp[2], lp[3], dst + 65536 + sw);
            }
        }
        CP_COMMIT();
    };

    load_chunk(0, tb);
    int stage = 0;
    for (int c = 0; c < nchunks; ++c) {
        CP_WAIT0();
        __syncthreads();
        if (c + 1 < nchunks) load_chunk(c + 1, tb + (stage ? 0 : STAGE_BYTES));
        const uint32_t base = tb + (stage ? STAGE_BYTES : 0);

        #pragma unroll
        for (int ks = 0; ks < 4; ++ks) {
            uint32_t Ah[2][4], Al[2][4], Bf[4][4];
            #pragma unroll
            for (int mm = 0; mm < 2; ++mm) {
                uint32_t ad = swadr(a_row + mm * 16, ks * 2 + a_k8);
                ldsm4(Ah[mm], base + ad);
                ldsm4(Al[mm], base + 16384 + ad);
            }
            // B-hi pass: Ah*Bh + Al*Bh
            #pragma unroll
            for (int nb = 0; nb < 4; ++nb) {
                uint32_t bd = swadr(b_row + nb * 16, ks * 2 + b_k8);
                ldsm4(Bf[nb], base + 32768 + bd);
            }
            #pragma unroll
            for (int mm = 0; mm < 2; ++mm)
                #pragma unroll
                for (int nb = 0; nb < 4; ++nb)
                    #pragma unroll
                    for (int h = 0; h < 2; ++h) {
                        mma16816(acc[mm][nb * 2 + h], Ah[mm], Bf[nb][h * 2], Bf[nb][h * 2 + 1]);
                        mma16816(acc[mm][nb * 2 + h], Al[mm], Bf[nb][h * 2], Bf[nb][h * 2 + 1]);
                    }
            // B-lo pass: Ah*Bl
            #pragma unroll
            for (int nb = 0; nb < 4; ++nb) {
                uint32_t bd = swadr(b_row + nb * 16, ks * 2 + b_k8);
                ldsm4(Bf[nb], base + 65536 + bd);
            }
            #pragma unroll
            for (int mm = 0; mm < 2; ++mm)
                #pragma unroll
                for (int nb = 0; nb < 4; ++nb)
                    #pragma unroll
                    for (int h = 0; h < 2; ++h)
                        mma16816(acc[mm][nb * 2 + h], Ah[mm], Bf[nb][h * 2], Bf[nb][h * 2 + 1]);
        }
        stage ^= 1;
    }
}

// ---------------------------------------------------------------------------
// Pre-convert kernels: fp32 -> bf16 hi/lo, pre-swizzled SMEM tile images
// ---------------------------------------------------------------------------
__global__ void k_cvt_w2(const float* __restrict__ cW, const float* __restrict__ aW)
{
    int chunk = blockIdx.x, slab = blockIdx.y, which = blockIdx.z;
    const float* W2 = (which ? aW : cW) + HH;
    unsigned char* out = g_w2bf + (size_t)(((which * 2 + slab) * 8) + chunk) * 65536;
    #pragma unroll
    for (int p = 0; p < 8; ++p) {
        int u = threadIdx.x + p * 256;               // 2048 units
        int row = u >> 3, seg = u & 7;
        uint32_t hp[4], lp[4];
        split8(W2 + (size_t)(slab * 256 + row) * (3 * HH) + chunk * 64 + seg * 8, hp, lp);
        uint32_t sw = swadr(row, seg);
        *reinterpret_cast<uint4*>(out + sw) = make_uint4(hp[0], hp[1], hp[2], hp[3]);
        *reinterpret_cast<uint4*>(out + 32768 + sw) = make_uint4(lp[0], lp[1], lp[2], lp[3]);
    }
}

__global__ void k_cvt_y()
{
    int chunk = blockIdx.x;                           // 16 chunks of K=1024
    unsigned char* out = g_ybf + (size_t)chunk * 32768;
    #pragma unroll
    for (int p = 0; p < 4; ++p) {
        int u = threadIdx.x + p * 256;               // 1024 units
        int row = u >> 3, seg = u & 7;
        uint32_t hp[4], lp[4];
        split8(g_y + (size_t)row * (2 * HH) + chunk * 64 + seg * 8, hp, lp);
        uint32_t sw = swadr(row, seg);
        *reinterpret_cast<uint4*>(out + sw) = make_uint4(hp[0], hp[1], hp[2], hp[3]);
        *reinterpret_cast<uint4*>(out + 16384 + sw) = make_uint4(lp[0], lp[1], lp[2], lp[3]);
    }
}

// ---------------------------------------------------------------------------
// Attention-score GEMM (both attentions in one launch, z = which).
// CTA: slab (256 j) x t; fused relu(.+Hh+cov*u)·v epilogue, deterministic.
// ---------------------------------------------------------------------------
__global__ void __launch_bounds__(512, 1)
k_scores_mma(const float* __restrict__ code, const float* __restrict__ ast,
             const float* __restrict__ cv,   const float* __restrict__ av,
             const float* __restrict__ ccov, const float* __restrict__ acov)
{
    extern __shared__ char smem[];
    __shared__ float sred[128][4];
    const uint32_t tb = (smem_to_u32(smem) + 127) & ~127u;

    const int slab = blockIdx.x, t = blockIdx.y, which = blockIdx.z;
    const int n0 = slab * 256;
    const float* enc = which ? ast : code;
    const float* v   = which ? av : cv;
    const float* cov = which ? acov : ccov;
    const unsigned char* bpre = g_w2bf + (size_t)((which * 2 + slab) * 8) * 65536;

    float acc[2][8][4];
    #pragma unroll
    for (int mm = 0; mm < 2; ++mm)
        #pragma unroll
        for (int nn = 0; nn < 8; ++nn)
            #pragma unroll
            for (int q = 0; q < 4; ++q) acc[mm][nn][q] = 0.f;

    mma_core256<false, true>(enc + (size_t)t * 128 * HH, HH, nullptr,
                             nullptr, 0, n0, 0, bpre, 8, tb, acc);

    const int lane = threadIdx.x & 31, wid = threadIdx.x >> 5;
    const int wm = wid & 3, wn = wid >> 2;
    const int quad = lane >> 2, tg = lane & 3;
    const float* Hh = g_Hh[which];
    const float* uu = g_u[which];

    #pragma unroll
    for (int mm = 0; mm < 2; ++mm) {
        #pragma unroll
        for (int half = 0; half < 2; ++half) {
            int b = wm * 32 + mm * 16 + quad + half * 8;
            float covv = cov[b * TT + t];
            const float* HhRow = Hh + (size_t)b * HH;
            float s = 0.f;
            #pragma unroll
            for (int nn = 0; nn < 8; ++nn) {
                int j = n0 + wn * 64 + nn * 8 + tg * 2;
                float p0 = acc[mm][nn][half * 2 + 0] + HhRow[j]     + covv * uu[j];
                float p1 = acc[mm][nn][half * 2 + 1] + HhRow[j + 1] + covv * uu[j + 1];
                s += fmaxf(p0, 0.f) * v[j] + fmaxf(p1, 0.f) * v[j + 1];
            }
            s += __shfl_xor_sync(0xffffffffu, s, 1);
            s += __shfl_xor_sync(0xffffffffu, s, 2);
            if (tg == 0) sred[b][wn] = s;
        }
    }
    __syncthreads();
    if (threadIdx.x < 128) {
        float s = sred[threadIdx.x][0] + sred[threadIdx.x][1]
                + sred[threadIdx.x][2] + sred[threadIdx.x][3];
        g_spart[which][slab][threadIdx.x * TT + t] = s;
    }
}

// ---------------------------------------------------------------------------
// Logits GEMM: out[0:B, n0:n0+256] = y @ Wout^T + bout (A pre-converted)
// ---------------------------------------------------------------------------
__global__ void __launch_bounds__(512, 1)
k_logits_mma(const float* __restrict__ Wout,   // [VOUT][1024]
             const float* __restrict__ bias,
             float* __restrict__ out)
{
    extern __shared__ char smem[];
    const uint32_t tb = (smem_to_u32(smem) + 127) & ~127u;
    const int n0 = blockIdx.x * 256;

    float acc[2][8][4];
    #pragma unroll
    for (int mm = 0; mm < 2; ++mm)
        #pragma unroll
        for (int nn = 0; nn < 8; ++nn)
            #pragma unroll
            for (int q = 0; q < 4; ++q) acc[mm][nn][q] = 0.f;

    mma_core256<true, false>(nullptr, 0, g_ybf,
                             Wout, 2 * HH, n0, VOUT - 1, nullptr, 16, tb, acc);

    const int lane = threadIdx.x & 31, wid = threadIdx.x >> 5;
    const int wm = wid & 3, wn = wid >> 2;
    const int quad = lane >> 2, tg = lane & 3;

    #pragma unroll
    for (int mm = 0; mm < 2; ++mm) {
        #pragma unroll
        for (int half = 0; half < 2; ++half) {
            int r = wm * 32 + mm * 16 + quad + half * 8;
            float* orow = out + (size_t)r * VOUT;
            #pragma unroll
            for (int nn = 0; nn < 8; ++nn) {
                int j = n0 + wn * 64 + nn * 8 + tg * 2;
                if (j < VOUT)
                    orow[j] = acc[mm][nn][half * 2 + 0] + bias[j];
                if (j + 1 < VOUT)
                    orow[j + 1] = acc[mm][nn][half * 2 + 1] + bias[j + 1];
            }
        }
    }
}

// ---------------------------------------------------------------------------
// Block reductions
// ---------------------------------------------------------------------------
__device__ __forceinline__ float warpMaxAll(float v) {
    #pragma unroll
    for (int o = 16; o; o >>= 1) v = fmaxf(v, __shfl_xor_sync(0xffffffffu, v, o));
    return v;
}
__device__ __forceinline__ float warpSumAll(float v) {
    #pragma unroll
    for (int o = 16; o; o >>= 1) v += __shfl_xor_sync(0xffffffffu, v, o);
    return v;
}
__device__ __forceinline__ float blockMax(float v, float* red, int nw) {
    int lane = threadIdx.x & 31, w = threadIdx.x >> 5;
    v = warpMaxAll(v);
    if (lane == 0) red[w] = v;
    __syncthreads();
    if (w == 0) {
        float r = (lane < nw) ? red[lane] : -1e30f;
        r = warpMaxAll(r);
        if (lane == 0) red[0] = r;
    }
    __syncthreads();
    float out = red[0];
    __syncthreads();
    return out;
}
__device__ __forceinline__ float blockSum(float v, float* red, int nw) {
    int lane = threadIdx.x & 31, w = threadIdx.x >> 5;
    v = warpSumAll(v);
    if (lane == 0) red[w] = v;
    __syncthreads();
    if (w == 0) {
        float r = (lane < nw) ? red[lane] : 0.f;
        r = warpSumAll(r);
        if (lane == 0) red[0] = r;
    }
    __syncthreads();
    float out = red[0];
    __syncthreads();
    return out;
}

// ---------------------------------------------------------------------------
// FFMA2 tiled NT-GEMM core
// ---------------------------------------------------------------------------
template <int BM, int BN, int BK, int TM, int TN>
__device__ __forceinline__ void gemm_core(
    const float* __restrict__ A, int lda,
    const float* __restrict__ Bm, int ldb,
    int m0, int n0, int N, int K,
    ull (&acc)[TM][TN / 2])
{
    constexpr int NTX = BN / TN;
    constexpr int THREADS = (BM / TM) * (BN / TN);
    constexpr int K4 = BK / 4;

    __shared__ __align__(16) float As[BK][BM + 4];
    __shared__ __align__(16) float Bs[BK][BN + 4];

    const int tid = threadIdx.x;
    const int tx = tid % NTX;
    const int ty = tid / NTX;

    for (int kt = 0; kt < K; kt += BK) {
        #pragma unroll
        for (int p = 0; p < (BM * K4) / THREADS; ++p) {
            int idx = tid + p * THREADS;
            int row = idx / K4;
            int kq  = (idx % K4) * 4;
            float4 v = *reinterpret_cast<const float4*>(
                A + (size_t)(m0 + row) * lda + kt + kq);
            As[kq + 0][row] = v.x; As[kq + 1][row] = v.y;
            As[kq + 2][row] = v.z; As[kq + 3][row] = v.w;
        }
        #pragma unroll
        for (int p = 0; p < (BN * K4) / THREADS; ++p) {
            int idx = tid + p * THREADS;
            int col = idx / K4;
            int kq  = (idx % K4) * 4;
            int j = n0 + col;
            float4 v = make_float4(0.f, 0.f, 0.f, 0.f);
            if (j < N)
                v = *reinterpret_cast<const float4*>(
                    Bm + (size_t)j * ldb + kt + kq);
            Bs[kq + 0][col] = v.x; Bs[kq + 1][col] = v.y;
            Bs[kq + 2][col] = v.z; Bs[kq + 3][col] = v.w;
        }
        __syncthreads();

        #pragma unroll 8
        for (int k = 0; k < BK; ++k) {
            float a[TM];
            #pragma unroll
            for (int c = 0; c < TM / 4; ++c) {
                float4 t4 = *reinterpret_cast<const float4*>(&As[k][ty * TM + 4 * c]);
                a[4 * c + 0] = t4.x; a[4 * c + 1] = t4.y;
                a[4 * c + 2] = t4.z; a[4 * c + 3] = t4.w;
            }
            ull Bv[TN / 2];
            #pragma unroll
            for (int c = 0; c < TN / 4; ++c) {
                double2 d = *reinterpret_cast<const double2*>(&Bs[k][tx * TN + 4 * c]);
                Bv[2 * c + 0] = __double_as_longlong(d.x);
                Bv[2 * c + 1] = __double_as_longlong(d.y);
            }
            #pragma unroll
            for (int i = 0; i < TM; ++i) {
                ull ad = dup2f(a[i]);
                #pragma unroll
                for (int q = 0; q < TN / 2; ++q)
                    acc[i][q] = ffma2(ad, Bv[q], acc[i][q]);
            }
        }
        __syncthreads();
    }
}

// Merged Hh GEMM: z -> (which, k-piece); C = g_HhP[which][zk]
__global__ void __launch_bounds__(256, 2)
k_hh(const float* __restrict__ h0,
     const float* __restrict__ cW, const float* __restrict__ aW,
     const float* __restrict__ cb, const float* __restrict__ ab)
{
    const int z = blockIdx.z, which = z >> 1, zk = z & 1;
    const float* A = h0 + zk * 256;
    const float* Bm = (which ? aW : cW) + zk * 256;
    const float* bias = which ? ab : cb;
    float* C = g_HhP[which][zk];

    ull acc[4][2];
    #pragma unroll
    for (int i = 0; i < 4; ++i) { acc[i][0] = 0ull; acc[i][1] = 0ull; }

    int m0 = blockIdx.y * 64, n0 = blockIdx.x * 64;
    gemm_core<64, 64, 32, 4, 4>(A, HH, Bm, 3 * HH, m0, n0, HH, 256, acc);

    int tx = threadIdx.x % 16, ty = threadIdx.x / 16;
    #pragma unroll
    for (int i = 0; i < 4; ++i) {
        size_t r = (size_t)(m0 + ty * 4 + i);
        #pragma unroll
        for (int q = 0; q < 2; ++q) {
            float2 c2 = unpack2(acc[i][q]);
            int j = n0 + tx * 4 + 2 * q;
            float b0 = zk == 0 ? bias[j] : 0.f;
            float b1 = zk == 0 ? bias[j + 1] : 0.f;
            C[r * HH + j]     = c2.x + b0;
            C[r * HH + j + 1] = c2.y + b1;
        }
    }
}

template <int BM, int BN, int BK, int TM, int TN>
__global__ void __launch_bounds__((BM / TM) * (BN / TN), 2)
k_gemm_sk(const float* __restrict__ A, int lda,
          const float* __restrict__ Bm, int ldb,
          const float* __restrict__ bias,
          float* __restrict__ C, int ldc, int N, int Kp, int Cz)
{
    const int z = blockIdx.z;
    A += (size_t)z * Kp;
    Bm += (size_t)z * Kp;
    C += (size_t)z * Cz;

    ull acc[TM][TN / 2];
    #pragma unroll
    for (int i = 0; i < TM; ++i)
        #pragma unroll
        for (int q = 0; q < TN / 2; ++q) acc[i][q] = 0ull;

    int m0 = blockIdx.y * BM, n0 = blockIdx.x * BN;
    gemm_core<BM, BN, BK, TM, TN>(A, lda, Bm, ldb, m0, n0, N, Kp, acc);

    int tx = threadIdx.x % (BN / TN), ty = threadIdx.x / (BN / TN);
    #pragma unroll
    for (int i = 0; i < TM; ++i) {
        size_t r = (size_t)(m0 + ty * TM + i);
        #pragma unroll
        for (int q = 0; q < TN / 2; ++q) {
            float2 c2 = unpack2(acc[i][q]);
            int j = n0 + tx * TN + 2 * q;
            float b0 = (z == 0) ? bias[j] : 0.f;
            float b1 = (z == 0 && j + 1 < N) ? bias[j + 1] : 0.f;
            if (j < N)     C[r * ldc + j]     = c2.x + b0;
            if (j + 1 < N) C[r * ldc + j + 1] = c2.y + b1;
        }
    }
}

// ---------------------------------------------------------------------------
// Small kernels
// ---------------------------------------------------------------------------
__global__ void k_emb(const int* __restrict__ inputs,
                      const float* __restrict__ emb)
{
    int idx = blockIdx.x * blockDim.x + threadIdx.x;   // B*E
    int b = idx >> 9, e = idx & 511;
    g_x[b * (EE + HH) + e] = emb[(size_t)inputs[b] * EE + e];
}

__global__ void k_u2(const float* __restrict__ cW, const float* __restrict__ cWc,
                     const float* __restrict__ aW, const float* __restrict__ aWc)
{
    int which = blockIdx.y;
    const float* W  = which ? aW : cW;
    const float* Wc = which ? aWc : cWc;
    int wid = threadIdx.x >> 5, lane = threadIdx.x & 31;
    int j0 = blockIdx.x * 32 + wid * 4;   // 16 blocks x 8 warps x 4 j
    #pragma unroll
    for (int jj = 0; jj < 4; ++jj) {
        int j = j0 + jj;
        const float* row = W + (size_t)j * (3 * HH) + 2 * HH;
        float s = 0.f;
        #pragma unroll
        for (int i = 0; i < 16; ++i)
            s += row[lane + 32 * i] * Wc[lane + 32 * i];
        s = warpSumAll(s);
        if (lane == 0) g_u[which][j] = s;
    }
}

__global__ void k_sum2()
{
    int i = blockIdx.x * blockDim.x + threadIdx.x;   // 2 * B*H = 131072
    int w = i >> 16, r = i & 65535;
    g_Hh[w][r] = g_HhP[w][0][r] + g_HhP[w][1][r];
}

// Fused softmax (both attentions) + context accumulation. One block per b.
__global__ void __launch_bounds__(512, 1)
k_smctx(const float* __restrict__ code, const float* __restrict__ ast,
        const float* __restrict__ covc, const float* __restrict__ cova,
        float* __restrict__ dout)
{
    int b = blockIdx.x;
    int t = threadIdx.x;          // 512 threads
    __shared__ float red[32];
    __shared__ float wgt2[2][TT];
    #pragma unroll
    for (int w = 0; w < 2; ++w) {
        int o = b * TT + t;
        float s = g_spart[w][0][o] + g_spart[w][1][o];
        float mx = blockMax(s, red, 16);
        float e = expf(s - mx);
        float sum = blockSum(e, red, 16);
        float wgt = e / sum;
        const float* cov = w ? cova : covc;
        wgt2[w][t] = wgt;
        dout[(w ? OFF_AW : OFF_CW) + o] = wgt;
        dout[(w ? OFF_ACOV : OFF_CCOV) + o] = cov[o] + wgt;
        __syncthreads();
    }
    // context: thread = h
    int h = threadIdx.x;
    const float* cp = code + (size_t)b * HH + h;
    const float* ap = ast  + (size_t)b * HH + h;
    float ac = 0.f, aa = 0.f;
    #pragma unroll 8
    for (int tt = 0; tt < TT; ++tt) {
        ac += wgt2[0][tt] * cp[(size_t)tt * (BB * HH)];
        aa += wgt2[1][tt] * ap[(size_t)tt * (BB * HH)];
    }
    float ctx = 0.5f * (ac + aa);
    g_x[b * (EE + HH) + EE + h] = ctx;
    g_y[b * (2 * HH) + HH + h] = ctx;
}

__global__ void k_gate(const float* __restrict__ h0, float* __restrict__ dout)
{
    int idx = blockIdx.x * blockDim.x + threadIdx.x;   // B*H
    int b = idx >> 9, h = idx & 511;
    int base = b * 3 * HH;
    float gi_r = g_gi[0][base + h]          + g_gi[1][base + h];
    float gi_z = g_gi[0][base + HH + h]     + g_gi[1][base + HH + h];
    float gi_n = g_gi[0][base + 2 * HH + h] + g_gi[1][base + 2 * HH + h];
    float gh_r = g_gh[0][base + h]          + g_gh[1][base + h];
    float gh_z = g_gh[0][base + HH + h]     + g_gh[1][base + HH + h];
    float gh_n = g_gh[0][base + 2 * HH + h] + g_gh[1][base + 2 * HH + h];
    float r = 1.f / (1.f + expf(-(gi_r + gh_r)));
    float z = 1.f / (1.f + expf(-(gi_z + gh_z)));
    float n = tanhf(gi_n + r * gh_n);
    float h1 = (1.f - z) * n + z * h0[idx];
    dout[OFF_H1 + idx] = h1;
    g_y[b * (2 * HH) + h] = h1;
}

__global__ void k_lsm(float* __restrict__ dout)
{
    int b = blockIdx.x;
    float* row = dout + (size_t)b * VOUT;
    __shared__ float red[32];
    float mx = -1e30f;
    for (int i = threadIdx.x; i < VOUT; i += blockDim.x) mx = fmaxf(mx, row[i]);
    mx = blockMax(mx, red, 16);
    float s = 0.f;
    for (int i = threadIdx.x; i < VOUT; i += blockDim.x) s += expf(row[i] - mx);
    s = blockSum(s, red, 16);
    float ls = logf(s);
    for (int i = threadIdx.x; i < VOUT; i += blockDim.x) row[i] = row[i] - mx - ls;
}

// ---------------------------------------------------------------------------
// Launch — ordered so k_scores_mma is launch #6 (ncu -s 5 -c 1 captures it)
// ---------------------------------------------------------------------------
extern "C" void kernel_launch(void* const* d_in, const int* in_sizes, int n_in,
                              void* d_out, int out_size)
{
    (void)in_sizes; (void)n_in; (void)out_size;

    const int*   inp   = (const int*)  d_in[0];
    const float* h0    = (const float*)d_in[1];   // [B,H]
    const float* code  = (const float*)d_in[2];   // [T,B,H]
    const float* ast   = (const float*)d_in[3];
    const float* ccov  = (const float*)d_in[4];   // [B,T]
    const float* acov  = (const float*)d_in[5];
    const float* emb   = (const float*)d_in[6];
    const float* cW    = (const float*)d_in[7];   // [H,3H]
    const float* cb    = (const float*)d_in[8];
    const float* cv    = (const float*)d_in[9];
    const float* cWc   = (const float*)d_in[10];
    const float* aW    = (const float*)d_in[11];
    const float* ab    = (const float*)d_in[12];
    const float* av    = (const float*)d_in[13];
    const float* aWc   = (const float*)d_in[14];
    const float* Wih   = (const float*)d_in[15];  // [3H, E+H]
    const float* Whh   = (const float*)d_in[16];  // [3H, H]
    const float* bih   = (const float*)d_in[17];
    const float* bhh   = (const float*)d_in[18];
    const float* Wout  = (const float*)d_in[19];  // [VOUT, 2H]
    const float* bout  = (const float*)d_in[20];
    float* out = (float*)d_out;

    float *p_x, *p_gi, *p_gh;
    cudaGetSymbolAddress((void**)&p_x,  g_x);
    cudaGetSymbolAddress((void**)&p_gi, g_gi);
    cudaGetSymbolAddress((void**)&p_gh, g_gh);

    cudaFuncSetAttribute(k_scores_mma,
        cudaFuncAttributeMaxDynamicSharedMemorySize, MMA_SMEM);
    cudaFuncSetAttribute(k_logits_mma,
        cudaFuncAttributeMaxDynamicSharedMemorySize, MMA_SMEM);

    // 1: W2 pre-convert (bf16 hi/lo swizzled images)
    k_cvt_w2<<<dim3(8, 2, 2), 256>>>(cW, aW);
    // 2: Hh = h0 @ W1^T + b_attn (both attentions, split-K 2, one launch)
    k_hh<<<dim3(8, 2, 4), 256>>>(h0, cW, aW, cb, ab);
    // 3: sum Hh partials
    k_sum2<<<512, 256>>>();
    // 4: rank-1 coverage weights
    k_u2<<<dim3(16, 2), 256>>>(cW, cWc, aW, aWc);
    // 5: embedding gather
    k_emb<<<256, 256>>>(inp, emb);
    // 6: attention-score GEMMs (PROFILED LAUNCH)
    k_scores_mma<<<dim3(2, 512, 2), 512, MMA_SMEM>>>(code, ast, cv, av, ccov, acov);
    // 7: fused softmax + context
    k_smctx<<<BB, 512>>>(code, ast, ccov, acov, out);
    // 8-9: GRU gate GEMMs (split-K 2; k_gate sums partials)
    k_gemm_sk<64, 64, 32, 4, 4><<<dim3(24, 2, 2), 256>>>(
        p_x, EE + HH, Wih, EE + HH, bih, p_gi, 3 * HH, 3 * HH, 512, BB * 3 * HH);
    k_gemm_sk<64, 64, 32, 4, 4><<<dim3(24, 2, 2), 256>>>(
        h0, HH, Whh, HH, bhh, p_gh, 3 * HH, 3 * HH, 256, BB * 3 * HH);
    // 10: GRU gate nonlinearity -> h1, y
    k_gate<<<256, 256>>>(h0, out);
    // 11: y pre-convert
    k_cvt_y<<<16, 256>>>();
    // 12: logits GEMM
    k_logits_mma<<<dim3((VOUT + 255) / 256, 1), 512, MMA_SMEM>>>(Wout, bout, out);
    // 13: log-softmax in place
    k_lsm<<<BB, 512>>>(out);
}

// round 11
// speedup vs baseline: 1.0019x; 1.0019x over previous
#include <cuda_runtime.h>
#include <cuda_bf16.h>
#include <cstdint>

// ---------------------------------------------------------------------------
// Problem constants
// ---------------------------------------------------------------------------
#define BB   128          // batch
#define TT   512          // time steps
#define HH   512          // hidden
#define EE   512          // embed dim
#define VOUT 30000

// output layout (flattened tuple): logits, h1, cw, aw, ccov, acov
#define OFF_H1   (BB * VOUT)
#define OFF_CW   (OFF_H1 + BB * HH)
#define OFF_AW   (OFF_CW + BB * TT)
#define OFF_CCOV (OFF_AW + BB * TT)
#define OFF_ACOV (OFF_CCOV + BB * TT)

typedef unsigned long long ull;

// ---------------------------------------------------------------------------
// Scratch (static device globals — no allocation)
// ---------------------------------------------------------------------------
__device__ float g_spart[2][2][BB * TT];     // partial scores, 2 j-slabs of 256
__device__ float g_Hh[2][BB * HH];           // h0 @ W1^T + b_attn (summed)
__device__ float g_HhP[2][2][BB * HH];       // split-K partials
__device__ float g_u[2][HH];                 // W3 @ Wc
__device__ float g_x[BB * (EE + HH)];        // GRU input [emb, ctx]
__device__ float g_y[BB * (2 * HH)];         // [h1, ctx]
__device__ float g_gi[2][BB * 3 * HH];       // split-K partials
__device__ float g_gh[2][BB * 3 * HH];
// pre-converted, pre-swizzled bf16 tile images
__device__ __align__(16) unsigned char g_w2bf[2 * 2 * 8 * 65536];  // 2MB
__device__ __align__(16) unsigned char g_ybf[16 * 32768];          // 512KB

// ---------------------------------------------------------------------------
// FFMA2 helpers (small GEMMs)
// ---------------------------------------------------------------------------
__device__ __forceinline__ ull dup2f(float x) {
    ull r;
    asm("mov.b64 %0, {%1, %1};" : "=l"(r) : "f"(x));
    return r;
}
__device__ __forceinline__ ull ffma2(ull a, ull b, ull c) {
    ull d;
    asm("fma.rn.f32x2 %0, %1, %2, %3;" : "=l"(d) : "l"(a), "l"(b), "l"(c));
    return d;
}
__device__ __forceinline__ float2 unpack2(ull v) {
    float x, y;
    asm("mov.b64 {%0, %1}, %2;" : "=f"(x), "=f"(y) : "l"(v));
    return make_float2(x, y);
}

// ---------------------------------------------------------------------------
// Tensor-core + async-copy primitives (sm_80-era: no 'a' target gating)
// ---------------------------------------------------------------------------
__device__ __forceinline__ uint32_t smem_to_u32(const void* p) {
    uint32_t a;
    asm("{ .reg .u64 t; cvta.to.shared.u64 t, %1; cvt.u32.u64 %0, t; }"
        : "=r"(a) : "l"(p));
    return a;
}
__device__ __forceinline__ void ldsm4(uint32_t (&r)[4], uint32_t addr) {
    asm volatile("ldmatrix.sync.aligned.m8n8.x4.shared.b16 {%0,%1,%2,%3}, [%4];"
                 : "=r"(r[0]), "=r"(r[1]), "=r"(r[2]), "=r"(r[3]) : "r"(addr));
}
__device__ __forceinline__ void mma16816(float (&c)[4],
    const uint32_t (&a)[4], uint32_t b0, uint32_t b1)
{
    asm volatile(
        "mma.sync.aligned.m16n8k16.row.col.f32.bf16.bf16.f32 "
        "{%0,%1,%2,%3}, {%4,%5,%6,%7}, {%8,%9}, {%0,%1,%2,%3};"
        : "+f"(c[0]), "+f"(c[1]), "+f"(c[2]), "+f"(c[3])
        : "r"(a[0]), "r"(a[1]), "r"(a[2]), "r"(a[3]), "r"(b0), "r"(b1));
}
#define STS128(r0, r1, r2, r3, smem_addr) \
    asm volatile("st.shared.v4.b32 [%0], {%1, %2, %3, %4};" \
        :: "r"(smem_addr), "r"(r0), "r"(r1), "r"(r2), "r"(r3) : "memory")
#define CP_ASYNC16(dst, src) \
    asm volatile("cp.async.cg.shared.global [%0], [%1], 16;" \
        :: "r"(dst), "l"(src) : "memory")
#define CP_COMMIT() asm volatile("cp.async.commit_group;" ::: "memory")
#define CP_WAIT0()  asm volatile("cp.async.wait_group 0;" ::: "memory")

// stage layout (bytes): A_HI 0 (16K), A_LO 16K, B_HI 32K (32K), B_LO 64K
#define STAGE_BYTES 98304
#define MMA_SMEM (2 * STAGE_BYTES + 128)   // + alignment slack

// swizzled byte offset for (row, 16B-seg) in a [rows x 128B] tile
__device__ __forceinline__ uint32_t swadr(int row, int seg) {
    uint32_t off = (uint32_t)(row * 128 + seg * 16);
    return off ^ (((uint32_t)(row & 7)) << 4);
}

// fp32x8 -> bf16 hi/lo split of one 16B-seg (8 values)
__device__ __forceinline__ void split8(const float* __restrict__ s,
                                       uint32_t (&hp)[4], uint32_t (&lp)[4])
{
    float4 x0 = *reinterpret_cast<const float4*>(s);
    float4 x1 = *reinterpret_cast<const float4*>(s + 4);
    float xs[8] = {x0.x, x0.y, x0.z, x0.w, x1.x, x1.y, x1.z, x1.w};
    #pragma unroll
    for (int p = 0; p < 4; ++p) {
        float a0 = xs[2 * p], a1 = xs[2 * p + 1];
        __nv_bfloat162 h = __floats2bfloat162_rn(a0, a1);
        float r0f = a0 - __bfloat162float(h.x);
        float r1f = a1 - __bfloat162float(h.y);
        __nv_bfloat162 l = __floats2bfloat162_rn(r0f, r1f);
        hp[p] = *reinterpret_cast<uint32_t*>(&h);
        lp[p] = *reinterpret_cast<uint32_t*>(&l);
    }
}

// ---------------------------------------------------------------------------
// Split-bf16 (3-pass) 128x256 tile GEMM core on mma.sync.
//   C[128,256](fp32) = A[128,K] @ B[n0:n0+256, K]^T
//   APRE: A via cp.async from pre-swizzled bf16 image (chunk stride 32KB)
//   BPRE: B via cp.async from pre-swizzled bf16 image (chunk stride 64KB)
//   512 threads, 16 warps (4 wm x 4 wn), warp tile 32x64, double-buffered.
// ---------------------------------------------------------------------------
template <bool APRE, bool BPRE>
__device__ __forceinline__ void mma_core256(
    const float* __restrict__ Afp, int lda,
    const unsigned char* __restrict__ apre,
    const float* __restrict__ Bfp, int ldb, int n0, int brow_last,
    const unsigned char* __restrict__ bpre,
    int nchunks, uint32_t tb, float (&acc)[2][8][4])
{
    const int tid  = threadIdx.x;
    const int lane = tid & 31;
    const int wid  = tid >> 5;
    const int wm   = wid & 3;
    const int wn   = wid >> 2;
    const int g  = lane >> 3;
    const int lr = lane & 7;
    const int a_row = wm * 32 + lr + (g & 1) * 8;
    const int a_k8  = g >> 1;
    const int b_row = wn * 64 + (g >> 1) * 8 + lr;
    const int b_k8  = g & 1;

    auto load_chunk = [&](int c, uint32_t dst) {
        if (APRE) {
            const unsigned char* src = apre + (size_t)c * 32768;
            #pragma unroll
            for (int p = 0; p < 4; ++p) {
                int i = tid + p * 512;                 // 2048 x 16B = 32KB
                CP_ASYNC16(dst + i * 16, src + i * 16);
            }
        } else {
            #pragma unroll
            for (int p = 0; p < 2; ++p) {
                int u = tid + p * 512;                 // 1024 units
                int row = u >> 3, seg = u & 7;
                uint32_t hp[4], lp[4];
                split8(Afp + (size_t)row * lda + c * 64 + seg * 8, hp, lp);
                uint32_t sw = swadr(row, seg);
                STS128(hp[0], hp[1], hp[2], hp[3], dst + sw);
                STS128(lp[0], lp[1], lp[2], lp[3], dst + 16384 + sw);
            }
        }
        if (BPRE) {
            const unsigned char* src = bpre + (size_t)c * 65536;
            #pragma unroll
            for (int p = 0; p < 8; ++p) {
                int i = tid + p * 512;                 // 4096 x 16B = 64KB
                CP_ASYNC16(dst + 32768 + i * 16, src + i * 16);
            }
        } else {
            #pragma unroll
            for (int p = 0; p < 4; ++p) {
                int u = tid + p * 512;                 // 2048 units, 256 rows
                int row = u >> 3, seg = u & 7;
                int rg = n0 + row;
                if (rg > brow_last) rg = brow_last;
                uint32_t hp[4], lp[4];
                split8(Bfp + (size_t)rg * ldb + c * 64 + seg * 8, hp, lp);
                uint32_t sw = swadr(row, seg);
                STS128(hp[0], hp[1], hp[2], hp[3], dst + 32768 + sw);
                STS128(lp[0], lp[1], lp[2], lp[3], dst + 65536 + sw);
            }
        }
        CP_COMMIT();
    };

    load_chunk(0, tb);
    int stage = 0;
    for (int c = 0; c < nchunks; ++c) {
        CP_WAIT0();
        __syncthreads();
        if (c + 1 < nchunks) load_chunk(c + 1, tb + (stage ? 0 : STAGE_BYTES));
        const uint32_t base = tb + (stage ? STAGE_BYTES : 0);

        #pragma unroll
        for (int ks = 0; ks < 4; ++ks) {
            uint32_t Ah[2][4], Al[2][4], Bf[4][4];
            #pragma unroll
            for (int mm = 0; mm < 2; ++mm) {
                uint32_t ad = swadr(a_row + mm * 16, ks * 2 + a_k8);
                ldsm4(Ah[mm], base + ad);
                ldsm4(Al[mm], base + 16384 + ad);
            }
            // B-hi pass: Ah*Bh + Al*Bh
            #pragma unroll
            for (int nb = 0; nb < 4; ++nb) {
                uint32_t bd = swadr(b_row + nb * 16, ks * 2 + b_k8);
                ldsm4(Bf[nb], base + 32768 + bd);
            }
            #pragma unroll
            for (int mm = 0; mm < 2; ++mm)
                #pragma unroll
                for (int nb = 0; nb < 4; ++nb)
                    #pragma unroll
                    for (int h = 0; h < 2; ++h) {
                        mma16816(acc[mm][nb * 2 + h], Ah[mm], Bf[nb][h * 2], Bf[nb][h * 2 + 1]);
                        mma16816(acc[mm][nb * 2 + h], Al[mm], Bf[nb][h * 2], Bf[nb][h * 2 + 1]);
                    }
            // B-lo pass: Ah*Bl
            #pragma unroll
            for (int nb = 0; nb < 4; ++nb) {
                uint32_t bd = swadr(b_row + nb * 16, ks * 2 + b_k8);
                ldsm4(Bf[nb], base + 65536 + bd);
            }
            #pragma unroll
            for (int mm = 0; mm < 2; ++mm)
                #pragma unroll
                for (int nb = 0; nb < 4; ++nb)
                    #pragma unroll
                    for (int h = 0; h < 2; ++h)
                        mma16816(acc[mm][nb * 2 + h], Ah[mm], Bf[nb][h * 2], Bf[nb][h * 2 + 1]);
        }
        stage ^= 1;
    }
}

// ---------------------------------------------------------------------------
// Pre-convert kernels: fp32 -> bf16 hi/lo, pre-swizzled SMEM tile images
// ---------------------------------------------------------------------------
__global__ void k_cvt_w2(const float* __restrict__ cW, const float* __restrict__ aW)
{
    int chunk = blockIdx.x, slab = blockIdx.y, which = blockIdx.z;
    const float* W2 = (which ? aW : cW) + HH;
    unsigned char* out = g_w2bf + (size_t)(((which * 2 + slab) * 8) + chunk) * 65536;
    #pragma unroll
    for (int p = 0; p < 8; ++p) {
        int u = threadIdx.x + p * 256;               // 2048 units
        int row = u >> 3, seg = u & 7;
        uint32_t hp[4], lp[4];
        split8(W2 + (size_t)(slab * 256 + row) * (3 * HH) + chunk * 64 + seg * 8, hp, lp);
        uint32_t sw = swadr(row, seg);
        *reinterpret_cast<uint4*>(out + sw) = make_uint4(hp[0], hp[1], hp[2], hp[3]);
        *reinterpret_cast<uint4*>(out + 32768 + sw) = make_uint4(lp[0], lp[1], lp[2], lp[3]);
    }
}

__global__ void k_cvt_y()
{
    int chunk = blockIdx.x;                           // 16 chunks of K=1024
    unsigned char* out = g_ybf + (size_t)chunk * 32768;
    #pragma unroll
    for (int p = 0; p < 4; ++p) {
        int u = threadIdx.x + p * 256;               // 1024 units
        int row = u >> 3, seg = u & 7;
        uint32_t hp[4], lp[4];
        split8(g_y + (size_t)row * (2 * HH) + chunk * 64 + seg * 8, hp, lp);
        uint32_t sw = swadr(row, seg);
        *reinterpret_cast<uint4*>(out + sw) = make_uint4(hp[0], hp[1], hp[2], hp[3]);
        *reinterpret_cast<uint4*>(out + 16384 + sw) = make_uint4(lp[0], lp[1], lp[2], lp[3]);
    }
}

// ---------------------------------------------------------------------------
// Attention-score GEMM (both attentions in one launch, z = which).
// CTA: slab (256 j) x t; fused relu(.+Hh+cov*u)·v epilogue, deterministic.
// ---------------------------------------------------------------------------
__global__ void __launch_bounds__(512, 1)
k_scores_mma(const float* __restrict__ code, const float* __restrict__ ast,
             const float* __restrict__ cv,   const float* __restrict__ av,
             const float* __restrict__ ccov, const float* __restrict__ acov)
{
    extern __shared__ char smem[];
    __shared__ float sred[128][4];
    const uint32_t tb = (smem_to_u32(smem) + 127) & ~127u;

    const int slab = blockIdx.x, t = blockIdx.y, which = blockIdx.z;
    const int n0 = slab * 256;
    const float* enc = which ? ast : code;
    const float* v   = which ? av : cv;
    const float* cov = which ? acov : ccov;
    const unsigned char* bpre = g_w2bf + (size_t)((which * 2 + slab) * 8) * 65536;

    float acc[2][8][4];
    #pragma unroll
    for (int mm = 0; mm < 2; ++mm)
        #pragma unroll
        for (int nn = 0; nn < 8; ++nn)
            #pragma unroll
            for (int q = 0; q < 4; ++q) acc[mm][nn][q] = 0.f;

    mma_core256<false, true>(enc + (size_t)t * 128 * HH, HH, nullptr,
                             nullptr, 0, n0, 0, bpre, 8, tb, acc);

    const int lane = threadIdx.x & 31, wid = threadIdx.x >> 5;
    const int wm = wid & 3, wn = wid >> 2;
    const int quad = lane >> 2, tg = lane & 3;
    const float* Hh = g_Hh[which];
    const float* uu = g_u[which];

    #pragma unroll
    for (int mm = 0; mm < 2; ++mm) {
        #pragma unroll
        for (int half = 0; half < 2; ++half) {
            int b = wm * 32 + mm * 16 + quad + half * 8;
            float covv = cov[b * TT + t];
            const float* HhRow = Hh + (size_t)b * HH;
            float s = 0.f;
            #pragma unroll
            for (int nn = 0; nn < 8; ++nn) {
                int j = n0 + wn * 64 + nn * 8 + tg * 2;
                float p0 = acc[mm][nn][half * 2 + 0] + HhRow[j]     + covv * uu[j];
                float p1 = acc[mm][nn][half * 2 + 1] + HhRow[j + 1] + covv * uu[j + 1];
                s += fmaxf(p0, 0.f) * v[j] + fmaxf(p1, 0.f) * v[j + 1];
            }
            s += __shfl_xor_sync(0xffffffffu, s, 1);
            s += __shfl_xor_sync(0xffffffffu, s, 2);
            if (tg == 0) sred[b][wn] = s;
        }
    }
    __syncthreads();
    if (threadIdx.x < 128) {
        float s = sred[threadIdx.x][0] + sred[threadIdx.x][1]
                + sred[threadIdx.x][2] + sred[threadIdx.x][3];
        g_spart[which][slab][threadIdx.x * TT + t] = s;
    }
}

// ---------------------------------------------------------------------------
// Logits GEMM: out[0:B, n0:n0+256] = y @ Wout^T + bout (A pre-converted)
// ---------------------------------------------------------------------------
__global__ void __launch_bounds__(512, 1)
k_logits_mma(const float* __restrict__ Wout,   // [VOUT][1024]
             const float* __restrict__ bias,
             float* __restrict__ out)
{
    extern __shared__ char smem[];
    const uint32_t tb = (smem_to_u32(smem) + 127) & ~127u;
    const int n0 = blockIdx.x * 256;

    float acc[2][8][4];
    #pragma unroll
    for (int mm = 0; mm < 2; ++mm)
        #pragma unroll
        for (int nn = 0; nn < 8; ++nn)
            #pragma unroll
            for (int q = 0; q < 4; ++q) acc[mm][nn][q] = 0.f;

    mma_core256<true, false>(nullptr, 0, g_ybf,
                             Wout, 2 * HH, n0, VOUT - 1, nullptr, 16, tb, acc);

    const int lane = threadIdx.x & 31, wid = threadIdx.x >> 5;
    const int wm = wid & 3, wn = wid >> 2;
    const int quad = lane >> 2, tg = lane & 3;

    #pragma unroll
    for (int mm = 0; mm < 2; ++mm) {
        #pragma unroll
        for (int half = 0; half < 2; ++half) {
            int r = wm * 32 + mm * 16 + quad + half * 8;
            float* orow = out + (size_t)r * VOUT;
            #pragma unroll
            for (int nn = 0; nn < 8; ++nn) {
                int j = n0 + wn * 64 + nn * 8 + tg * 2;
                if (j < VOUT)
                    orow[j] = acc[mm][nn][half * 2 + 0] + bias[j];
                if (j + 1 < VOUT)
                    orow[j + 1] = acc[mm][nn][half * 2 + 1] + bias[j + 1];
            }
        }
    }
}

// ---------------------------------------------------------------------------
// Block reductions
// ---------------------------------------------------------------------------
__device__ __forceinline__ float warpMaxAll(float v) {
    #pragma unroll
    for (int o = 16; o; o >>= 1) v = fmaxf(v, __shfl_xor_sync(0xffffffffu, v, o));
    return v;
}
__device__ __forceinline__ float warpSumAll(float v) {
    #pragma unroll
    for (int o = 16; o; o >>= 1) v += __shfl_xor_sync(0xffffffffu, v, o);
    return v;
}
__device__ __forceinline__ float blockMax(float v, float* red, int nw) {
    int lane = threadIdx.x & 31, w = threadIdx.x >> 5;
    v = warpMaxAll(v);
    if (lane == 0) red[w] = v;
    __syncthreads();
    if (w == 0) {
        float r = (lane < nw) ? red[lane] : -1e30f;
        r = warpMaxAll(r);
        if (lane == 0) red[0] = r;
    }
    __syncthreads();
    float out = red[0];
    __syncthreads();
    return out;
}
__device__ __forceinline__ float blockSum(float v, float* red, int nw) {
    int lane = threadIdx.x & 31, w = threadIdx.x >> 5;
    v = warpSumAll(v);
    if (lane == 0) red[w] = v;
    __syncthreads();
    if (w == 0) {
        float r = (lane < nw) ? red[lane] : 0.f;
        r = warpSumAll(r);
        if (lane == 0) red[0] = r;
    }
    __syncthreads();
    float out = red[0];
    __syncthreads();
    return out;
}

// ---------------------------------------------------------------------------
// FFMA2 tiled NT-GEMM core
// ---------------------------------------------------------------------------
template <int BM, int BN, int BK, int TM, int TN>
__device__ __forceinline__ void gemm_core(
    const float* __restrict__ A, int lda,
    const float* __restrict__ Bm, int ldb,
    int m0, int n0, int N, int K,
    ull (&acc)[TM][TN / 2])
{
    constexpr int NTX = BN / TN;
    constexpr int THREADS = (BM / TM) * (BN / TN);
    constexpr int K4 = BK / 4;

    __shared__ __align__(16) float As[BK][BM + 4];
    __shared__ __align__(16) float Bs[BK][BN + 4];

    const int tid = threadIdx.x;
    const int tx = tid % NTX;
    const int ty = tid / NTX;

    for (int kt = 0; kt < K; kt += BK) {
        #pragma unroll
        for (int p = 0; p < (BM * K4) / THREADS; ++p) {
            int idx = tid + p * THREADS;
            int row = idx / K4;
            int kq  = (idx % K4) * 4;
            float4 v = *reinterpret_cast<const float4*>(
                A + (size_t)(m0 + row) * lda + kt + kq);
            As[kq + 0][row] = v.x; As[kq + 1][row] = v.y;
            As[kq + 2][row] = v.z; As[kq + 3][row] = v.w;
        }
        #pragma unroll
        for (int p = 0; p < (BN * K4) / THREADS; ++p) {
            int idx = tid + p * THREADS;
            int col = idx / K4;
            int kq  = (idx % K4) * 4;
            int j = n0 + col;
            float4 v = make_float4(0.f, 0.f, 0.f, 0.f);
            if (j < N)
                v = *reinterpret_cast<const float4*>(
                    Bm + (size_t)j * ldb + kt + kq);
            Bs[kq + 0][col] = v.x; Bs[kq + 1][col] = v.y;
            Bs[kq + 2][col] = v.z; Bs[kq + 3][col] = v.w;
        }
        __syncthreads();

        #pragma unroll 8
        for (int k = 0; k < BK; ++k) {
            float a[TM];
            #pragma unroll
            for (int c = 0; c < TM / 4; ++c) {
                float4 t4 = *reinterpret_cast<const float4*>(&As[k][ty * TM + 4 * c]);
                a[4 * c + 0] = t4.x; a[4 * c + 1] = t4.y;
                a[4 * c + 2] = t4.z; a[4 * c + 3] = t4.w;
            }
            ull Bv[TN / 2];
            #pragma unroll
            for (int c = 0; c < TN / 4; ++c) {
                double2 d = *reinterpret_cast<const double2*>(&Bs[k][tx * TN + 4 * c]);
                Bv[2 * c + 0] = __double_as_longlong(d.x);
                Bv[2 * c + 1] = __double_as_longlong(d.y);
            }
            #pragma unroll
            for (int i = 0; i < TM; ++i) {
                ull ad = dup2f(a[i]);
                #pragma unroll
                for (int q = 0; q < TN / 2; ++q)
                    acc[i][q] = ffma2(ad, Bv[q], acc[i][q]);
            }
        }
        __syncthreads();
    }
}

// Merged Hh GEMM: z -> (which, k-piece); C = g_HhP[which][zk]
__global__ void __launch_bounds__(256, 2)
k_hh(const float* __restrict__ h0,
     const float* __restrict__ cW, const float* __restrict__ aW,
     const float* __restrict__ cb, const float* __restrict__ ab)
{
    const int z = blockIdx.z, which = z >> 1, zk = z & 1;
    const float* A = h0 + zk * 256;
    const float* Bm = (which ? aW : cW) + zk * 256;
    const float* bias = which ? ab : cb;
    float* C = g_HhP[which][zk];

    ull acc[4][2];
    #pragma unroll
    for (int i = 0; i < 4; ++i) { acc[i][0] = 0ull; acc[i][1] = 0ull; }

    int m0 = blockIdx.y * 64, n0 = blockIdx.x * 64;
    gemm_core<64, 64, 32, 4, 4>(A, HH, Bm, 3 * HH, m0, n0, HH, 256, acc);

    int tx = threadIdx.x % 16, ty = threadIdx.x / 16;
    #pragma unroll
    for (int i = 0; i < 4; ++i) {
        size_t r = (size_t)(m0 + ty * 4 + i);
        #pragma unroll
        for (int q = 0; q < 2; ++q) {
            float2 c2 = unpack2(acc[i][q]);
            int j = n0 + tx * 4 + 2 * q;
            float b0 = zk == 0 ? bias[j] : 0.f;
            float b1 = zk == 0 ? bias[j + 1] : 0.f;
            C[r * HH + j]     = c2.x + b0;
            C[r * HH + j + 1] = c2.y + b1;
        }
    }
}

template <int BM, int BN, int BK, int TM, int TN>
__global__ void __launch_bounds__((BM / TM) * (BN / TN), 2)
k_gemm_sk(const float* __restrict__ A, int lda,
          const float* __restrict__ Bm, int ldb,
          const float* __restrict__ bias,
          float* __restrict__ C, int ldc, int N, int Kp, int Cz)
{
    const int z = blockIdx.z;
    A += (size_t)z * Kp;
    Bm += (size_t)z * Kp;
    C += (size_t)z * Cz;

    ull acc[TM][TN / 2];
    #pragma unroll
    for (int i = 0; i < TM; ++i)
        #pragma unroll
        for (int q = 0; q < TN / 2; ++q) acc[i][q] = 0ull;

    int m0 = blockIdx.y * BM, n0 = blockIdx.x * BN;
    gemm_core<BM, BN, BK, TM, TN>(A, lda, Bm, ldb, m0, n0, N, Kp, acc);

    int tx = threadIdx.x % (BN / TN), ty = threadIdx.x / (BN / TN);
    #pragma unroll
    for (int i = 0; i < TM; ++i) {
        size_t r = (size_t)(m0 + ty * TM + i);
        #pragma unroll
        for (int q = 0; q < TN / 2; ++q) {
            float2 c2 = unpack2(acc[i][q]);
            int j = n0 + tx * TN + 2 * q;
            float b0 = (z == 0) ? bias[j] : 0.f;
            float b1 = (z == 0 && j + 1 < N) ? bias[j + 1] : 0.f;
            if (j < N)     C[r * ldc + j]     = c2.x + b0;
            if (j + 1 < N) C[r * ldc + j + 1] = c2.y + b1;
        }
    }
}

// ---------------------------------------------------------------------------
// Small kernels
// ---------------------------------------------------------------------------
__global__ void k_emb(const int* __restrict__ inputs,
                      const float* __restrict__ emb)
{
    int idx = blockIdx.x * blockDim.x + threadIdx.x;   // B*E
    int b = idx >> 9, e = idx & 511;
    g_x[b * (EE + HH) + e] = emb[(size_t)inputs[b] * EE + e];
}

__global__ void k_u2(const float* __restrict__ cW, const float* __restrict__ cWc,
                     const float* __restrict__ aW, const float* __restrict__ aWc)
{
    int which = blockIdx.y;
    const float* W  = which ? aW : cW;
    const float* Wc = which ? aWc : cWc;
    int wid = threadIdx.x >> 5, lane = threadIdx.x & 31;
    int j0 = blockIdx.x * 32 + wid * 4;   // 16 blocks x 8 warps x 4 j
    #pragma unroll
    for (int jj = 0; jj < 4; ++jj) {
        int j = j0 + jj;
        const float* row = W + (size_t)j * (3 * HH) + 2 * HH;
        float s = 0.f;
        #pragma unroll
        for (int i = 0; i < 16; ++i)
            s += row[lane + 32 * i] * Wc[lane + 32 * i];
        s = warpSumAll(s);
        if (lane == 0) g_u[which][j] = s;
    }
}

__global__ void k_sum2()
{
    int i = blockIdx.x * blockDim.x + threadIdx.x;   // 2 * B*H = 131072
    int w = i >> 16, r = i & 65535;
    g_Hh[w][r] = g_HhP[w][0][r] + g_HhP[w][1][r];
}

// Fused softmax (both attentions) + context accumulation. One block per b.
__global__ void __launch_bounds__(512, 1)
k_smctx(const float* __restrict__ code, const float* __restrict__ ast,
        const float* __restrict__ covc, const float* __restrict__ cova,
        float* __restrict__ dout)
{
    int b = blockIdx.x;
    int t = threadIdx.x;          // 512 threads
    __shared__ float red[32];
    __shared__ float wgt2[2][TT];
    #pragma unroll
    for (int w = 0; w < 2; ++w) {
        int o = b * TT + t;
        float s = g_spart[w][0][o] + g_spart[w][1][o];
        float mx = blockMax(s, red, 16);
        float e = expf(s - mx);
        float sum = blockSum(e, red, 16);
        float wgt = e / sum;
        const float* cov = w ? cova : covc;
        wgt2[w][t] = wgt;
        dout[(w ? OFF_AW : OFF_CW) + o] = wgt;
        dout[(w ? OFF_ACOV : OFF_CCOV) + o] = cov[o] + wgt;
        __syncthreads();
    }
    // context: thread = h
    int h = threadIdx.x;
    const float* cp = code + (size_t)b * HH + h;
    const float* ap = ast  + (size_t)b * HH + h;
    float ac = 0.f, aa = 0.f;
    #pragma unroll 8
    for (int tt = 0; tt < TT; ++tt) {
        ac += wgt2[0][tt] * cp[(size_t)tt * (BB * HH)];
        aa += wgt2[1][tt] * ap[(size_t)tt * (BB * HH)];
    }
    float ctx = 0.5f * (ac + aa);
    g_x[b * (EE + HH) + EE + h] = ctx;
    g_y[b * (2 * HH) + HH + h] = ctx;
}

__global__ void k_gate(const float* __restrict__ h0, float* __restrict__ dout)
{
    int idx = blockIdx.x * blockDim.x + threadIdx.x;   // B*H
    int b = idx >> 9, h = idx & 511;
    int base = b * 3 * HH;
    float gi_r = g_gi[0][base + h]          + g_gi[1][base + h];
    float gi_z = g_gi[0][base + HH + h]     + g_gi[1][base + HH + h];
    float gi_n = g_gi[0][base + 2 * HH + h] + g_gi[1][base + 2 * HH + h];
    float gh_r = g_gh[0][base + h]          + g_gh[1][base + h];
    float gh_z = g_gh[0][base + HH + h]     + g_gh[1][base + HH + h];
    float gh_n = g_gh[0][base + 2 * HH + h] + g_gh[1][base + 2 * HH + h];
    float r = 1.f / (1.f + expf(-(gi_r + gh_r)));
    float z = 1.f / (1.f + expf(-(gi_z + gh_z)));
    float n = tanhf(gi_n + r * gh_n);
    float h1 = (1.f - z) * n + z * h0[idx];
    dout[OFF_H1 + idx] = h1;
    g_y[b * (2 * HH) + h] = h1;
}

__global__ void k_lsm(float* __restrict__ dout)
{
    int b = blockIdx.x;
    float* row = dout + (size_t)b * VOUT;
    __shared__ float red[32];
    float mx = -1e30f;
    for (int i = threadIdx.x; i < VOUT; i += blockDim.x) mx = fmaxf(mx, row[i]);
    mx = blockMax(mx, red, 16);
    float s = 0.f;
    for (int i = threadIdx.x; i < VOUT; i += blockDim.x) s += expf(row[i] - mx);
    s = blockSum(s, red, 16);
    float ls = logf(s);
    for (int i = threadIdx.x; i < VOUT; i += blockDim.x) row[i] = row[i] - mx - ls;
}

// ---------------------------------------------------------------------------
// Launch — ordered so k_scores_mma is launch #6 (ncu -s 5 -c 1 captures it)
// ---------------------------------------------------------------------------
extern "C" void kernel_launch(void* const* d_in, const int* in_sizes, int n_in,
                              void* d_out, int out_size)
{
    (void)in_sizes; (void)n_in; (void)out_size;

    const int*   inp   = (const int*)  d_in[0];
    const float* h0    = (const float*)d_in[1];   // [B,H]
    const float* code  = (const float*)d_in[2];   // [T,B,H]
    const float* ast   = (const float*)d_in[3];
    const float* ccov  = (const float*)d_in[4];   // [B,T]
    const float* acov  = (const float*)d_in[5];
    const float* emb   = (const float*)d_in[6];
    const float* cW    = (const float*)d_in[7];   // [H,3H]
    const float* cb    = (const float*)d_in[8];
    const float* cv    = (const float*)d_in[9];
    const float* cWc   = (const float*)d_in[10];
    const float* aW    = (const float*)d_in[11];
    const float* ab    = (const float*)d_in[12];
    const float* av    = (const float*)d_in[13];
    const float* aWc   = (const float*)d_in[14];
    const float* Wih   = (const float*)d_in[15];  // [3H, E+H]
    const float* Whh   = (const float*)d_in[16];  // [3H, H]
    const float* bih   = (const float*)d_in[17];
    const float* bhh   = (const float*)d_in[18];
    const float* Wout  = (const float*)d_in[19];  // [VOUT, 2H]
    const float* bout  = (const float*)d_in[20];
    float* out = (float*)d_out;

    float *p_x, *p_gi, *p_gh;
    cudaGetSymbolAddress((void**)&p_x,  g_x);
    cudaGetSymbolAddress((void**)&p_gi, g_gi);
    cudaGetSymbolAddress((void**)&p_gh, g_gh);

    cudaFuncSetAttribute(k_scores_mma,
        cudaFuncAttributeMaxDynamicSharedMemorySize, MMA_SMEM);
    cudaFuncSetAttribute(k_logits_mma,
        cudaFuncAttributeMaxDynamicSharedMemorySize, MMA_SMEM);

    // 1: W2 pre-convert (bf16 hi/lo swizzled images)
    k_cvt_w2<<<dim3(8, 2, 2), 256>>>(cW, aW);
    // 2: Hh = h0 @ W1^T + b_attn (both attentions, split-K 2, one launch)
    k_hh<<<dim3(8, 2, 4), 256>>>(h0, cW, aW, cb, ab);
    // 3: sum Hh partials
    k_sum2<<<512, 256>>>();
    // 4: rank-1 coverage weights
    k_u2<<<dim3(16, 2), 256>>>(cW, cWc, aW, aWc);
    // 5: embedding gather
    k_emb<<<256, 256>>>(inp, emb);
    // 6: attention-score GEMMs (PROFILED LAUNCH)
    k_scores_mma<<<dim3(2, 512, 2), 512, MMA_SMEM>>>(code, ast, cv, av, ccov, acov);
    // 7: fused softmax + context
    k_smctx<<<BB, 512>>>(code, ast, ccov, acov, out);
    // 8-9: GRU gate GEMMs (split-K 2; k_gate sums partials)
    k_gemm_sk<64, 64, 32, 4, 4><<<dim3(24, 2, 2), 256>>>(
        p_x, EE + HH, Wih, EE + HH, bih, p_gi, 3 * HH, 3 * HH, 512, BB * 3 * HH);
    k_gemm_sk<64, 64, 32, 4, 4><<<dim3(24, 2, 2), 256>>>(
        h0, HH, Whh, HH, bhh, p_gh, 3 * HH, 3 * HH, 256, BB * 3 * HH);
    // 10: GRU gate nonlinearity -> h1, y
    k_gate<<<256, 256>>>(h0, out);
    // 11: y pre-convert
    k_cvt_y<<<16, 256>>>();
    // 12: logits GEMM
    k_logits_mma<<<dim3((VOUT + 255) / 256, 1), 512, MMA_SMEM>>>(Wout, bout, out);
    // 13: log-softmax in place
    k_lsm<<<BB, 512>>>(out);
}